// round 4
// baseline (speedup 1.0000x reference)
#include <cuda_runtime.h>
#include <cstddef>

#define N_USER  100000
#define N_MOVIE 20000
#define D_IN    64
#define HID     128
#define OUT_D   64
#define NEDGE   600000

typedef unsigned long long ULL;

// ---------------------------------------------------------------------------
// Scratch
// ---------------------------------------------------------------------------
__device__ int g_deg_u[N_USER];
__device__ int g_deg_m[N_MOVIE];
__device__ int g_off_u[N_USER];
__device__ int g_off_m[N_MOVIE];
__device__ int g_cur_u[N_USER];
__device__ int g_cur_m[N_MOVIE];
__device__ int g_adj_u[NEDGE];
__device__ int g_adj_m[NEDGE];
__device__ int g_part_u[128];
__device__ int g_part_m[32];

__device__ float g_agg_user [N_USER  * D_IN];
__device__ float g_agg_movie[N_MOVIE * D_IN];
__device__ float g_agg_user2[N_USER  * HID];
__device__ float g_user_x  [N_USER  * HID];
__device__ float g_movie_x [N_MOVIE * HID];
__device__ float g_movieP  [N_MOVIE * HID];
__device__ float g_user_h  [N_USER  * HID];

// ---------------------------------------------------------------------------
// Packed f32x2 helpers
// ---------------------------------------------------------------------------
__device__ __forceinline__ ULL pack2(float x, float y) {
    ULL r;
    asm("mov.b64 %0, {%1, %2};" : "=l"(r) : "f"(x), "f"(y));
    return r;
}
__device__ __forceinline__ float2 unpack2(ULL v) {
    float2 r;
    asm("mov.b64 {%0, %1}, %2;" : "=f"(r.x), "=f"(r.y) : "l"(v));
    return r;
}
__device__ __forceinline__ ULL ffma2u(ULL a, ULL b, ULL c) {
    ULL d;
    asm("fma.rn.f32x2 %0, %1, %2, %3;" : "=l"(d) : "l"(a), "l"(b), "l"(c));
    return d;
}

// ---------------------------------------------------------------------------
// CSR build
// ---------------------------------------------------------------------------
__global__ void zero_counts() {
    int i = blockIdx.x * blockDim.x + threadIdx.x;
    if (i < N_USER)  g_deg_u[i] = 0;
    if (i < N_MOVIE) g_deg_m[i] = 0;
}

__global__ __launch_bounds__(256) void hist_kernel(
    const int* __restrict__ eu, const int* __restrict__ em)
{
    int e = blockIdx.x * blockDim.x + threadIdx.x;
    if (e >= NEDGE) return;
    atomicAdd(&g_deg_u[eu[e]], 1);
    atomicAdd(&g_deg_m[em[e]], 1);
}

__global__ __launch_bounds__(1024) void scan_block_kernel(
    const int* __restrict__ deg, int* __restrict__ off,
    int* __restrict__ part, int n)
{
    __shared__ int s[1024];
    int t = threadIdx.x;
    int i = blockIdx.x * 1024 + t;
    int v = (i < n) ? deg[i] : 0;
    s[t] = v;
    __syncthreads();
    #pragma unroll
    for (int d = 1; d < 1024; d <<= 1) {
        int x = (t >= d) ? s[t - d] : 0;
        __syncthreads();
        s[t] += x;
        __syncthreads();
    }
    if (i < n) off[i] = s[t] - v;
    if (t == 1023) part[blockIdx.x] = s[1023];
}

__global__ __launch_bounds__(128) void scan_partials_kernel(int nu, int nm) {
    __shared__ int s[128];
    int t = threadIdx.x;
    int v = (t < nu) ? g_part_u[t] : 0;
    s[t] = v;
    __syncthreads();
    #pragma unroll
    for (int d = 1; d < 128; d <<= 1) {
        int x = (t >= d) ? s[t - d] : 0;
        __syncthreads();
        s[t] += x;
        __syncthreads();
    }
    if (t < nu) g_part_u[t] = s[t] - v;
    __syncthreads();
    v = (t < nm) ? g_part_m[t] : 0;
    s[t] = v;
    __syncthreads();
    #pragma unroll
    for (int d = 1; d < 128; d <<= 1) {
        int x = (t >= d) ? s[t - d] : 0;
        __syncthreads();
        s[t] += x;
        __syncthreads();
    }
    if (t < nm) g_part_m[t] = s[t] - v;
}

__global__ __launch_bounds__(256) void add_offsets_kernel(
    int* __restrict__ off, int* __restrict__ cur,
    const int* __restrict__ part, int n)
{
    int i = blockIdx.x * blockDim.x + threadIdx.x;
    if (i >= n) return;
    int o = off[i] + part[i >> 10];
    off[i] = o;
    cur[i] = o;
}

__global__ __launch_bounds__(256) void fill_kernel(
    const int* __restrict__ eu, const int* __restrict__ em)
{
    int e = blockIdx.x * blockDim.x + threadIdx.x;
    if (e >= NEDGE) return;
    int u = eu[e], m = em[e];
    int su = atomicAdd(&g_cur_u[u], 1);
    g_adj_u[su] = m;
    int sm = atomicAdd(&g_cur_m[m], 1);
    g_adj_m[sm] = u;
}

// ---------------------------------------------------------------------------
// Gather-mean: one warp per destination node, 4-way MLP unroll.
// ---------------------------------------------------------------------------
template<int D>
__global__ __launch_bounds__(256) void gather_mean(
    const float* __restrict__ src, const int* __restrict__ adj,
    const int* __restrict__ off, const int* __restrict__ deg,
    float* __restrict__ dst, int n)
{
    int w = (blockIdx.x * 256 + threadIdx.x) >> 5;
    int lane = threadIdx.x & 31;
    if (w >= n) return;
    int o = off[w], d = deg[w];
    float sc = 1.0f / (float)max(d, 1);
    if constexpr (D == 64) {
        float2 acc = make_float2(0.f, 0.f);
        int i = 0;
        for (; i + 4 <= d; i += 4) {
            int s0 = __ldg(&adj[o + i + 0]);
            int s1 = __ldg(&adj[o + i + 1]);
            int s2 = __ldg(&adj[o + i + 2]);
            int s3 = __ldg(&adj[o + i + 3]);
            float2 v0 = __ldg(&((const float2*)src)[(size_t)s0 * 32 + lane]);
            float2 v1 = __ldg(&((const float2*)src)[(size_t)s1 * 32 + lane]);
            float2 v2 = __ldg(&((const float2*)src)[(size_t)s2 * 32 + lane]);
            float2 v3 = __ldg(&((const float2*)src)[(size_t)s3 * 32 + lane]);
            acc.x += v0.x + v1.x + v2.x + v3.x;
            acc.y += v0.y + v1.y + v2.y + v3.y;
        }
        for (; i < d; i++) {
            int s = __ldg(&adj[o + i]);
            float2 v = __ldg(&((const float2*)src)[(size_t)s * 32 + lane]);
            acc.x += v.x; acc.y += v.y;
        }
        ((float2*)dst)[(size_t)w * 32 + lane] = make_float2(acc.x * sc, acc.y * sc);
    } else {
        float4 acc = make_float4(0.f, 0.f, 0.f, 0.f);
        int i = 0;
        for (; i + 4 <= d; i += 4) {
            int s0 = __ldg(&adj[o + i + 0]);
            int s1 = __ldg(&adj[o + i + 1]);
            int s2 = __ldg(&adj[o + i + 2]);
            int s3 = __ldg(&adj[o + i + 3]);
            float4 v0 = __ldg(&((const float4*)src)[(size_t)s0 * 32 + lane]);
            float4 v1 = __ldg(&((const float4*)src)[(size_t)s1 * 32 + lane]);
            float4 v2 = __ldg(&((const float4*)src)[(size_t)s2 * 32 + lane]);
            float4 v3 = __ldg(&((const float4*)src)[(size_t)s3 * 32 + lane]);
            acc.x += v0.x + v1.x + v2.x + v3.x;
            acc.y += v0.y + v1.y + v2.y + v3.y;
            acc.z += v0.z + v1.z + v2.z + v3.z;
            acc.w += v0.w + v1.w + v2.w + v3.w;
        }
        for (; i < d; i++) {
            int s = __ldg(&adj[o + i]);
            float4 v = __ldg(&((const float4*)src)[(size_t)s * 32 + lane]);
            acc.x += v.x; acc.y += v.y; acc.z += v.z; acc.w += v.w;
        }
        ((float4*)dst)[(size_t)w * 32 + lane] =
            make_float4(acc.x * sc, acc.y * sc, acc.z * sc, acc.w * sc);
    }
}

// ---------------------------------------------------------------------------
// Register-tiled FFMA2 GEMM-combine.
//   out[M,N] = act( A[M,128] @ W[128,N] (+agg) (+bias) ),
//   A = [xa | xb] when TWO (two K=64 sources), else xb (K=128).
// Thread tile: 8 strided column-pairs x 2 rows. Weights in smem as
// [pair][k] ULL pairs with KPAD=130 (conflict-free 8-lane LDS.128).
// x read straight from global (L1/L2); no per-tile barriers.
// ---------------------------------------------------------------------------
#define KTOT 128
#define KPAD 130

template<int N, int KB, int LD>
__device__ __forceinline__ void mm_half(
    const float* __restrict__ src, int rc0, int rc1, int kofs,
    int ct, const ULL* __restrict__ sWT, ULL acc[8][2])
{
    constexpr int COLTH = N / 16;
    const float2* s0 = (const float2*)(src + (size_t)rc0 * LD);
    const float2* s1 = (const float2*)(src + (size_t)rc1 * LD);
    #pragma unroll 4
    for (int kb = 0; kb < KB; kb += 2) {
        float2 a0 = __ldg(&s0[kb >> 1]);
        float2 a1 = __ldg(&s1[kb >> 1]);
        ULL x00 = pack2(a0.x, a0.x), x01 = pack2(a0.y, a0.y);
        ULL x10 = pack2(a1.x, a1.x), x11 = pack2(a1.y, a1.y);
        int kk = kofs + kb;
        #pragma unroll
        for (int j = 0; j < 8; j++) {
            int p = ct + COLTH * j;
            ulonglong2 wv = *(const ulonglong2*)&sWT[p * KPAD + kk];
            acc[j][0] = ffma2u(x00, wv.x, acc[j][0]);
            acc[j][0] = ffma2u(x01, wv.y, acc[j][0]);
            acc[j][1] = ffma2u(x10, wv.x, acc[j][1]);
            acc[j][1] = ffma2u(x11, wv.y, acc[j][1]);
        }
    }
}

template<int N, bool TWO, bool AGG, bool RELU, bool BIAS>
__global__ __launch_bounds__(256, 2) void combine2(
    const float* __restrict__ xa, const float* __restrict__ xb,
    const float* __restrict__ Wa, const float* __restrict__ Wb,
    const float* __restrict__ agg, const float* __restrict__ bias,
    float* __restrict__ out, int nrows)
{
    constexpr int COLTH = N / 16;         // 8 (N=128) or 4 (N=64)
    constexpr int ROWTH = 256 / COLTH;
    constexpr int ROWS  = ROWTH * 2;      // 64 (N=128) or 128 (N=64)

    extern __shared__ __align__(16) ULL sWT[];   // [N/2][KPAD]

    const int tid = threadIdx.x;
    const int ct  = tid % COLTH;
    const int rt  = tid / COLTH;

    // Stage weights once per (persistent) block: sWT[p][k] = (W[k][2p], W[k][2p+1])
    for (int i = tid; i < (N / 2) * KTOT; i += 256) {
        int p = i / KTOT, k = i % KTOT;
        const float* Wrow;
        if constexpr (TWO) {
            Wrow = (k < 64) ? (Wa + (size_t)k * N) : (Wb + (size_t)(k - 64) * N);
        } else {
            Wrow = Wb + (size_t)k * N;
        }
        sWT[p * KPAD + k] = pack2(Wrow[2 * p], Wrow[2 * p + 1]);
    }
    __syncthreads();

    float2 breg[8];
    if constexpr (BIAS) {
        #pragma unroll
        for (int j = 0; j < 8; j++)
            breg[j] = ((const float2*)bias)[ct + COLTH * j];
    }

    const int ntiles = (nrows + ROWS - 1) / ROWS;
    for (int tile = blockIdx.x; tile < ntiles; tile += gridDim.x) {
        const int r0 = tile * ROWS + rt * 2;
        const int r1 = r0 + 1;
        const int rc0 = min(r0, nrows - 1);
        const int rc1 = min(r1, nrows - 1);

        ULL acc[8][2];
        #pragma unroll
        for (int j = 0; j < 8; j++) { acc[j][0] = 0ull; acc[j][1] = 0ull; }

        if constexpr (TWO) {
            mm_half<N, 64, 64>(xa, rc0, rc1, 0,  ct, sWT, acc);
            mm_half<N, 64, 64>(xb, rc0, rc1, 64, ct, sWT, acc);
        } else {
            mm_half<N, KTOT, KTOT>(xb, rc0, rc1, 0, ct, sWT, acc);
        }

        #pragma unroll
        for (int r = 0; r < 2; r++) {
            int row = (r == 0) ? r0 : r1;
            if (row < nrows) {
                #pragma unroll
                for (int j = 0; j < 8; j++) {
                    int p = ct + COLTH * j;
                    float2 o = unpack2(acc[j][r]);
                    if constexpr (BIAS) { o.x += breg[j].x; o.y += breg[j].y; }
                    if constexpr (AGG) {
                        float2 g = __ldg(&((const float2*)agg)[(size_t)row * (N / 2) + p]);
                        o.x += g.x; o.y += g.y;
                    }
                    if constexpr (RELU) { o.x = fmaxf(o.x, 0.f); o.y = fmaxf(o.y, 0.f); }
                    ((float2*)out)[(size_t)row * (N / 2) + p] = o;
                }
            }
        }
    }
}

// ---------------------------------------------------------------------------
// kernel_launch
// ---------------------------------------------------------------------------
extern "C" void kernel_launch(void* const* d_in, const int* in_sizes, int n_in,
                              void* d_out, int out_size) {
    const float* x_user  = (const float*)d_in[0];
    const float* x_movie = (const float*)d_in[1];
    const int*   eu      = (const int*)d_in[2];
    const int*   em      = (const int*)d_in[3];
    const float* W1l     = (const float*)d_in[4];
    const float* W1r     = (const float*)d_in[5];
    const float* b1      = (const float*)d_in[6];
    const float* W2l     = (const float*)d_in[7];
    const float* W2r     = (const float*)d_in[8];
    const float* b2      = (const float*)d_in[9];
    const float* W3l     = (const float*)d_in[10];
    const float* W3r     = (const float*)d_in[11];
    const float* b3      = (const float*)d_in[12];
    const float* Wlin1   = (const float*)d_in[13];
    const float* blin1   = (const float*)d_in[14];
    const float* Wlin2   = (const float*)d_in[15];
    const float* blin2   = (const float*)d_in[16];

    float* out_user  = (float*)d_out;
    float* out_movie = out_user + (size_t)N_USER * OUT_D;

    int *p_deg_u, *p_deg_m, *p_off_u, *p_off_m, *p_cur_u, *p_cur_m;
    int *p_adj_u, *p_adj_m, *p_part_u, *p_part_m;
    float *p_agg_user, *p_agg_movie, *p_agg_user2;
    float *p_user_x, *p_movie_x, *p_movieP, *p_user_h;
    cudaGetSymbolAddress((void**)&p_deg_u, g_deg_u);
    cudaGetSymbolAddress((void**)&p_deg_m, g_deg_m);
    cudaGetSymbolAddress((void**)&p_off_u, g_off_u);
    cudaGetSymbolAddress((void**)&p_off_m, g_off_m);
    cudaGetSymbolAddress((void**)&p_cur_u, g_cur_u);
    cudaGetSymbolAddress((void**)&p_cur_m, g_cur_m);
    cudaGetSymbolAddress((void**)&p_adj_u, g_adj_u);
    cudaGetSymbolAddress((void**)&p_adj_m, g_adj_m);
    cudaGetSymbolAddress((void**)&p_part_u, g_part_u);
    cudaGetSymbolAddress((void**)&p_part_m, g_part_m);
    cudaGetSymbolAddress((void**)&p_agg_user,  g_agg_user);
    cudaGetSymbolAddress((void**)&p_agg_movie, g_agg_movie);
    cudaGetSymbolAddress((void**)&p_agg_user2, g_agg_user2);
    cudaGetSymbolAddress((void**)&p_user_x,    g_user_x);
    cudaGetSymbolAddress((void**)&p_movie_x,   g_movie_x);
    cudaGetSymbolAddress((void**)&p_movieP,    g_movieP);
    cudaGetSymbolAddress((void**)&p_user_h,    g_user_h);

    const int SM128 = (128 / 2) * KPAD * 8;   // 66560
    const int SM64  = (64 / 2)  * KPAD * 8;   // 33280

    cudaFuncSetAttribute((const void*)combine2<128, true,  false, true,  true>,
                         cudaFuncAttributeMaxDynamicSharedMemorySize, SM128);
    cudaFuncSetAttribute((const void*)combine2<128, false, false, false, false>,
                         cudaFuncAttributeMaxDynamicSharedMemorySize, SM128);
    cudaFuncSetAttribute((const void*)combine2<128, false, true,  true,  true>,
                         cudaFuncAttributeMaxDynamicSharedMemorySize, SM128);
    cudaFuncSetAttribute((const void*)combine2<64,  false, false, false, true>,
                         cudaFuncAttributeMaxDynamicSharedMemorySize, SM64);

    const int GRID = 296;                          // 2 persistent blocks/SM
    const int GRID_M128 = (N_MOVIE + 63) / 64;     // 313 tiles -> capped below
    const int GRID_M = (GRID_M128 < GRID) ? GRID_M128 : GRID;

    const int NBU = (N_USER  + 1023) / 1024;
    const int NBM = (N_MOVIE + 1023) / 1024;

    // CSR build
    zero_counts<<<(N_USER + 255) / 256, 256>>>();
    hist_kernel<<<(NEDGE + 255) / 256, 256>>>(eu, em);
    scan_block_kernel<<<NBU, 1024>>>(p_deg_u, p_off_u, p_part_u, N_USER);
    scan_block_kernel<<<NBM, 1024>>>(p_deg_m, p_off_m, p_part_m, N_MOVIE);
    scan_partials_kernel<<<1, 128>>>(NBU, NBM);
    add_offsets_kernel<<<(N_USER + 255) / 256, 256>>>(p_off_u, p_cur_u, p_part_u, N_USER);
    add_offsets_kernel<<<(N_MOVIE + 255) / 256, 256>>>(p_off_m, p_cur_m, p_part_m, N_MOVIE);
    fill_kernel<<<(NEDGE + 255) / 256, 256>>>(eu, em);

    // conv1 + conv2 aggregation (gather means)
    gather_mean<D_IN><<<(N_USER * 32 + 255) / 256, 256>>>(
        x_movie, p_adj_u, p_off_u, p_deg_u, p_agg_user, N_USER);
    gather_mean<D_IN><<<(N_MOVIE * 32 + 255) / 256, 256>>>(
        x_user, p_adj_m, p_off_m, p_deg_m, p_agg_movie, N_MOVIE);

    // conv1: user_x = relu([agg_user|x_user] @ [W1l;W1r] + b1)
    combine2<128, true, false, true, true><<<GRID, 256, SM128>>>(
        p_agg_user, x_user, W1l, W1r, nullptr, b1, p_user_x, N_USER);

    // conv2: movie_x = relu([agg_movie|x_movie] @ [W2l;W2r] + b2)
    combine2<128, true, false, true, true><<<GRID_M, 256, SM128>>>(
        p_agg_movie, x_movie, W2l, W2r, nullptr, b2, p_movie_x, N_MOVIE);

    // movieP = movie_x @ W3l (projected before aggregation)
    combine2<128, false, false, false, false><<<GRID_M, 256, SM128>>>(
        nullptr, p_movie_x, nullptr, W3l, nullptr, nullptr, p_movieP, N_MOVIE);

    // conv3 aggregation
    gather_mean<HID><<<(N_USER * 32 + 255) / 256, 256>>>(
        p_movieP, p_adj_u, p_off_u, p_deg_u, p_agg_user2, N_USER);

    // conv3: user_h = relu(agg_user2 + user_x @ W3r + b3)
    combine2<128, false, true, true, true><<<GRID, 256, SM128>>>(
        nullptr, p_user_x, nullptr, W3r, p_agg_user2, b3, p_user_h, N_USER);

    // out_user = user_h @ Wlin1 + blin1
    combine2<64, false, false, false, true><<<GRID, 256, SM64>>>(
        nullptr, p_user_h, nullptr, Wlin1, nullptr, blin1, out_user, N_USER);

    // out_movie = movie_x @ Wlin2 + blin2
    combine2<64, false, false, false, true><<<GRID_M, 256, SM64>>>(
        nullptr, p_movie_x, nullptr, Wlin2, nullptr, blin2, out_movie, N_MOVIE);
}